// round 16
// baseline (speedup 1.0000x reference)
#include <cuda_runtime.h>
#include <cuda_bf16.h>
#include <math.h>
#include <stdint.h>

// ---------------- problem constants ----------------
#define HID 256          // H
#define NHEAD 4
#define DHEAD 64
#define BATCH 256        // B
#define SEQL 128         // L
#define TT 256           // T
#define TS 255           // T-1 scan steps
#define RROWS (TS*BATCH) // 65280
#define NNODE (BATCH*SEQL) // 32768
#define G3 768           // 3*H

// ---------------- device scratch (static, no allocs) ----------------
__device__ int   g_is64;
__device__ float g_XW[NNODE*HID];
__device__ float g_ASD[NNODE*8];
__device__ float g_ROUT[NNODE*HID];
__device__ float g_ROUTT[BATCH*HID*SEQL];
__device__ float g_H0[BATCH*HID];
__device__ float g_COLV[G3];                 // w_ih[:,256] rate column
__device__ float g_GI[RROWS*G3];
__device__ float g_RIN[RROWS*512];           // [h_t | weighted] rows
__device__ float g_DOT[RROWS*8];             // fc2 partial dots
__device__ uint4 g_WPK[24576];               // W_hh packed bf16 fragments (scan)
__device__ uint4 g_PIH[49152];               // W_ih^T packed split-bf16 fragments
__device__ uint4 g_PF1[65536];               // fc1_w^T packed split-bf16 fragments
__device__ uint4 g_PXW[16384];               // gat_w packed split-bf16 fragments

// ---------------- small utility kernels ----------------
__global__ void k_detect(const int* __restrict__ t) {
    if (threadIdx.x == 0) {
        int all0 = 1;
        for (int q = 1; q < 256; q += 2) if (t[q] != 0) { all0 = 0; break; }
        g_is64 = all0;
    }
}

__global__ void k_memset(float* p, int n) {
    int i = blockIdx.x * blockDim.x + threadIdx.x;
    if (i < n) p[i] = 0.f;
}

// extract rate column: colv[n] = w_ih[n*257 + 256]
__global__ void k_col(const float* __restrict__ wih, float* __restrict__ colv) {
    int n = blockIdx.x * blockDim.x + threadIdx.x;
    if (n < G3) colv[n] = wih[n * 257 + 256];
}

__device__ __forceinline__ uint32_t pkbf(float a, float b) {
    return (uint32_t)__bfloat16_as_ushort(__float2bfloat16(a)) |
           ((uint32_t)__bfloat16_as_ushort(__float2bfloat16(b)) << 16);
}
__device__ __forceinline__ float bfhi(float a) {
    return __bfloat162float(__float2bfloat16(a));
}

// pack W_hh (768x256 row-major) into bf16 m16n8k16 B-fragments for the 4-CTA scan.
// index: (((rank*4 + w)*16 + c)*3 + tp)*32 + lane
// rank r, warp w (<4) cover local cols jl in [0,192):
//   j = (jl>>6)*256 + r*64 + (jl&63)
__global__ void k_packbf4(const float* __restrict__ whh) {
    int gid = blockIdx.x * 256 + threadIdx.x;     // 0..24575
    int lane = gid & 31;
    int q = gid >> 5;                             // 0..767
    int tp3 = q % 3;
    int t2 = q / 3;
    int c = t2 & 15;
    int t3 = t2 >> 4;                             // 0..15
    int w = t3 & 3, r = t3 >> 2;
    int grp = lane >> 2, thr = lane & 3;
    int jl0 = w * 48 + (2 * tp3) * 8 + grp;
    int jl1 = jl0 + 8;
    int j0 = (jl0 >> 6) * 256 + r * 64 + (jl0 & 63);
    int j1 = (jl1 >> 6) * 256 + r * 64 + (jl1 & 63);
    int kb = c * 16 + 2 * thr;
    const float* W0 = whh + j0 * 256;
    const float* W1 = whh + j1 * 256;
    uint4 v;
    v.x = pkbf(W0[kb],     W0[kb + 1]);
    v.y = pkbf(W0[kb + 8], W0[kb + 9]);
    v.z = pkbf(W1[kb],     W1[kb + 1]);
    v.w = pkbf(W1[kb + 8], W1[kb + 9]);
    g_WPK[gid] = v;
}

// pack K-major B[K][N] (element (k,n) at B[k*N+n]) into split-bf16 fragments.
__global__ void k_packsplit(const float* __restrict__ B, int N, int K, uint4* out) {
    int gid = blockIdx.x * 256 + threadIdx.x;
    int total = (N >> 3) * (K >> 4) * 32;
    if (gid >= total) return;
    int lane = gid & 31, q = gid >> 5;
    int chunks = K >> 4;
    int chunk = q % chunks, ntile = q / chunks;
    int grp = lane >> 2, thr = lane & 3;
    int n = ntile * 8 + grp;
    int k0 = chunk * 16 + 2 * thr;
    float x0 = B[(long long)k0 * N + n];
    float x1 = B[(long long)(k0 + 1) * N + n];
    float x2 = B[(long long)(k0 + 8) * N + n];
    float x3 = B[(long long)(k0 + 9) * N + n];
    float h0 = bfhi(x0), h1 = bfhi(x1), h2 = bfhi(x2), h3 = bfhi(x3);
    uint4 v;
    v.x = pkbf(h0, h1);
    v.y = pkbf(h2, h3);
    v.z = pkbf(x0 - h0, x1 - h1);
    v.w = pkbf(x2 - h2, x3 - h3);
    out[gid] = v;
}

// transposed source: element (k,n) at src[n*ld + k]  (row-major weights)
__global__ void k_packsplitT(const float* __restrict__ src, int N, int K, int ld,
                             uint4* out) {
    int gid = blockIdx.x * 256 + threadIdx.x;
    int total = (N >> 3) * (K >> 4) * 32;
    if (gid >= total) return;
    int lane = gid & 31, q = gid >> 5;
    int chunks = K >> 4;
    int chunk = q % chunks, ntile = q / chunks;
    int grp = lane >> 2, thr = lane & 3;
    int n = ntile * 8 + grp;
    int k0 = chunk * 16 + 2 * thr;
    const float* row = src + (long long)n * ld;
    float x0 = row[k0];
    float x1 = row[k0 + 1];
    float x2 = row[k0 + 8];
    float x3 = row[k0 + 9];
    float h0 = bfhi(x0), h1 = bfhi(x1), h2 = bfhi(x2), h3 = bfhi(x3);
    uint4 v;
    v.x = pkbf(h0, h1);
    v.y = pkbf(h2, h3);
    v.z = pkbf(x0 - h0, x1 - h1);
    v.w = pkbf(x2 - h2, x3 - h3);
    out[gid] = v;
}

// ---------------- GAT: a_src / a_dst projections ----------------
__global__ void k_asd(const float* __restrict__ asrc, const float* __restrict__ adst) {
    __shared__ float ss[HID], sd[HID];
    int t = threadIdx.x;
    ss[t] = asrc[t]; sd[t] = adst[t];
    __syncthreads();
    int gid = blockIdx.x * 256 + t;
    int n = gid >> 2, h = gid & 3;
    const float* x = &g_XW[n * HID + h * DHEAD];
    const float* cs = &ss[h * DHEAD];
    const float* cd = &sd[h * DHEAD];
    float s = 0.f, d = 0.f;
#pragma unroll 8
    for (int q = 0; q < DHEAD; q++) { float v = x[q]; s += v * cs[q]; d += v * cd[q]; }
    g_ASD[n * 8 + h] = s;
    g_ASD[n * 8 + 4 + h] = d;
}

// ---------------- GAT aggregate + residual + LayerNorm ----------------
__global__ void k_gat(const float* __restrict__ emb, const float* __restrict__ bias,
                      const float* __restrict__ gamma, const float* __restrict__ beta) {
    int i = blockIdx.x;
    int j = threadIdx.x;
    int h = j >> 6;
    int l = i & (SEQL - 1);
    float ad = g_ASD[i * 8 + 4 + h];
    bool v0 = (l > 0), v1 = (l < SEQL - 1);
    float e0 = -1e30f, e1 = -1e30f;
    if (v0) { float e = g_ASD[(i - 1) * 8 + h] + ad; e0 = e > 0.f ? e : 0.2f * e; }
    if (v1) { float e = g_ASD[(i + 1) * 8 + h] + ad; e1 = e > 0.f ? e : 0.2f * e; }
    float emax = fmaxf(e0, e1);
    float x0 = v0 ? expf(e0 - emax) : 0.f;
    float x1 = v1 ? expf(e1 - emax) : 0.f;
    float inv = 1.f / (x0 + x1 + 1e-16f);
    float a0 = x0 * inv, a1 = x1 * inv;
    float val = bias[j] + emb[(long long)i * HID + j];
    if (v0) val += a0 * g_XW[(i - 1) * HID + j];
    if (v1) val += a1 * g_XW[(i + 1) * HID + j];
    __shared__ float red[HID];
    red[j] = val; __syncthreads();
    for (int s = 128; s > 0; s >>= 1) { if (j < s) red[j] += red[j + s]; __syncthreads(); }
    float mean = red[0] * (1.f / HID); __syncthreads();
    float dv = val - mean;
    red[j] = dv * dv; __syncthreads();
    for (int s = 128; s > 0; s >>= 1) { if (j < s) red[j] += red[j + s]; __syncthreads(); }
    float var = red[0] * (1.f / HID);
    g_ROUT[(long long)i * HID + j] = dv * rsqrtf(var + 1e-5f) * gamma[j] + beta[j];
}

__global__ void k_hidden0() {
    int b = blockIdx.x, j = threadIdx.x;
    const float* p = &g_ROUT[(long long)b * SEQL * HID + j];
    float s = 0.f;
    for (int l = 0; l < SEQL; l++) s += p[l * HID];
    g_H0[b * HID + j] = s * (1.f / SEQL);
}

// (b,l,h) -> (b,h,l)
__global__ void k_routt() {
    __shared__ float tile[32][33];
    int b = blockIdx.z;
    int h0 = blockIdx.x * 32, l0 = blockIdx.y * 32;
    int x = threadIdx.x, y = threadIdx.y;
    const float* in = &g_ROUT[(long long)b * SEQL * HID];
    float* out = &g_ROUTT[(long long)b * HID * SEQL];
    for (int yy = y; yy < 32; yy += 8) tile[yy][x] = in[(l0 + yy) * HID + h0 + x];
    __syncthreads();
    for (int yy = y; yy < 32; yy += 8) out[(h0 + yy) * SEQL + l0 + x] = tile[x][yy];
}

// ---------------- generic tiled fp32 SGEMM (scores / weighted) ----------------
// doSoftmax: requires gridDim.x==1 (full N row per block); writes softmaxed,
// mask-zeroed attn directly.
__global__ __launch_bounds__(256, 2) void k_sgemm(
    int M, int N, int K,
    const float* __restrict__ A, int lda, long long sA,
    const float* __restrict__ B, int ldb, long long sB,
    float* __restrict__ C, int ldc, long long sC,
    const int* __restrict__ maskPtr, int maskStride,
    float alpha, int doSoftmax)
{
    __shared__ float As[8][128];
    __shared__ float Bs[8][128];
    const float* Ab = A + (long long)blockIdx.z * sA;
    const float* Bb = B + (long long)blockIdx.z * sB;
    float* Cb = C + (long long)blockIdx.z * sC;
    int m0 = blockIdx.y * 128, n0 = blockIdx.x * 128;
    int tid = threadIdx.x, tx = tid & 15, ty = tid >> 4;
    float acc[8][8];
#pragma unroll
    for (int i = 0; i < 8; i++)
#pragma unroll
        for (int j = 0; j < 8; j++) acc[i][j] = 0.f;

    int rowL = tid >> 1, kq = (tid & 1) * 4;
    int grow = m0 + rowL; if (grow > M - 1) grow = M - 1;
    const float* Arow = Ab + (long long)grow * lda;
    int kB = tid >> 5, nq = (tid & 31) * 4;

    for (int k0 = 0; k0 < K; k0 += 8) {
        float4 av = *(const float4*)(Arow + k0 + kq);
        As[kq + 0][rowL] = av.x; As[kq + 1][rowL] = av.y;
        As[kq + 2][rowL] = av.z; As[kq + 3][rowL] = av.w;
        *(float4*)&Bs[kB][nq] = *(const float4*)(Bb + (long long)(k0 + kB) * ldb + n0 + nq);
        __syncthreads();
#pragma unroll
        for (int kk = 0; kk < 8; kk++) {
            float a[8], b[8];
            *(float4*)&a[0] = *(const float4*)&As[kk][ty * 4];
            *(float4*)&a[4] = *(const float4*)&As[kk][64 + ty * 4];
            *(float4*)&b[0] = *(const float4*)&Bs[kk][tx * 4];
            *(float4*)&b[4] = *(const float4*)&Bs[kk][64 + tx * 4];
#pragma unroll
            for (int i = 0; i < 8; i++)
#pragma unroll
                for (int j = 0; j < 8; j++) acc[i][j] += a[i] * b[j];
        }
        __syncthreads();
    }

    if (doSoftmax) {
        const int* mkz = maskPtr + (long long)blockIdx.z * maskStride;
#pragma unroll
        for (int i = 0; i < 8; i++) {
            int mloc = (i < 4) ? ty * 4 + i : 64 + ty * 4 + (i - 4);
            int m = m0 + mloc;
            float v[8]; int nl[8]; int vld[8];
#pragma unroll
            for (int j = 0; j < 8; j++) {
                nl[j] = (j < 4) ? tx * 4 + j : 64 + tx * 4 + (j - 4);
                vld[j] = mkz[n0 + nl[j]];
                float x = acc[i][j] * alpha;
                v[j] = vld[j] ? x : -1e30f;
            }
            float mx = v[0];
#pragma unroll
            for (int j = 1; j < 8; j++) mx = fmaxf(mx, v[j]);
            for (int o = 1; o < 16; o <<= 1)
                mx = fmaxf(mx, __shfl_xor_sync(0xffffffffu, mx, o));
            float s = 0.f;
#pragma unroll
            for (int j = 0; j < 8; j++) { v[j] = expf(v[j] - mx); s += v[j]; }
            for (int o = 1; o < 16; o <<= 1)
                s += __shfl_xor_sync(0xffffffffu, s, o);
            float inv = 1.f / s;
            if (m < M) {
#pragma unroll
                for (int j = 0; j < 8; j++)
                    Cb[(long long)m * ldc + n0 + nl[j]] = vld[j] ? v[j] * inv : 0.f;
            }
        }
        return;
    }

#pragma unroll
    for (int i = 0; i < 8; i++) {
        int mloc = (i < 4) ? ty * 4 + i : 64 + ty * 4 + (i - 4);
        int m = m0 + mloc;
        if (m >= M) continue;
#pragma unroll
        for (int j = 0; j < 8; j++) {
            int nloc = (j < 4) ? tx * 4 + j : 64 + tx * 4 + (j - 4);
            int n = n0 + nloc;
            Cb[(long long)m * ldc + n] = acc[i][j] * alpha;
        }
    }
}

// ---------------- bf16 mma + helpers ----------------
__device__ __forceinline__ void mma16816(float* c, uint32_t a0, uint32_t a1,
                                         uint32_t a2, uint32_t a3,
                                         uint32_t b0, uint32_t b1) {
    asm volatile(
        "mma.sync.aligned.m16n8k16.row.col.f32.bf16.bf16.f32 "
        "{%0,%1,%2,%3},{%4,%5,%6,%7},{%8,%9},{%0,%1,%2,%3};"
        : "+f"(c[0]), "+f"(c[1]), "+f"(c[2]), "+f"(c[3])
        : "r"(a0), "r"(a1), "r"(a2), "r"(a3), "r"(b0), "r"(b1));
}

__device__ __forceinline__ uint32_t sm2u(const void* p) {
    return (uint32_t)__cvta_generic_to_shared(p);
}

__device__ __forceinline__ void ldsm4(uint32_t* d, uint32_t saddr) {
    asm volatile("ldmatrix.sync.aligned.m8n8.x4.shared.b16 {%0,%1,%2,%3}, [%4];"
        : "=r"(d[0]), "=r"(d[1]), "=r"(d[2]), "=r"(d[3]) : "r"(saddr));
}

// ---------------- split-bf16 GEMM (double-buffered A, ldmatrix fragments) --------
#define ABLK (128*20*4)          // bytes of one [128][20] u32 block
__global__ __launch_bounds__(256, 2) void k_bgemm(
    int M, int N, int K,
    const float* __restrict__ A, int lda,
    const void* __restrict__ gth,
    const uint4* __restrict__ Bp,
    float* __restrict__ C, int ldc,
    const float* __restrict__ rowScal, const float* __restrict__ rowVec,
    const float* __restrict__ bias, int doRelu,
    const float* __restrict__ dotW, float* __restrict__ dotPart)
{
    __shared__ uint32_t Ab[2][2][128][20];

    int m0 = blockIdx.y * 128, n0 = blockIdx.x * 128;
    int tid = threadIdx.x;

    int rloc = tid >> 1, kq = (tid & 1) * 16;
    const float* Arow;
    {
        int grow = m0 + rloc;
        if (gth) {
            long long gr = g_is64 ? ((const long long*)gth)[grow]
                                  : (long long)((const int*)gth)[grow];
            Arow = A + gr * (long long)lda;
        } else {
            Arow = A + (long long)grow * lda;
        }
    }

    int wid = tid >> 5, lane = tid & 31;
    int wm = wid & 3, wn = wid >> 2;
    int mBase = wm * 32;
    int grp = lane >> 2, thr = lane & 3;
    int chunksPerN = K >> 4;
    int ntBase = (n0 >> 3) + wn * 8;

    uint32_t aBase = sm2u(&Ab[0][0][lane & 15][(lane >> 4) << 2]);
    uint32_t rowOff0 = (uint32_t)(mBase) * 80;
    uint32_t rowOff1 = (uint32_t)(mBase + 16) * 80;

    float acc[2][8][4];
#pragma unroll
    for (int mt = 0; mt < 2; mt++)
#pragma unroll
        for (int nt = 0; nt < 8; nt++)
#pragma unroll
            for (int q = 0; q < 4; q++) acc[mt][nt][q] = 0.f;

    float4 avr[4];
    auto load_regs = [&](int k0) {
#pragma unroll
        for (int i = 0; i < 4; i++)
            avr[i] = *(const float4*)(Arow + k0 + kq + 4 * i);
    };
    auto split_store = [&](int s) {
        float h[16], l[16];
#pragma unroll
        for (int i = 0; i < 4; i++) {
            float4 av = avr[i];
            h[4*i+0] = bfhi(av.x); h[4*i+1] = bfhi(av.y);
            h[4*i+2] = bfhi(av.z); h[4*i+3] = bfhi(av.w);
            l[4*i+0] = av.x - h[4*i+0]; l[4*i+1] = av.y - h[4*i+1];
            l[4*i+2] = av.z - h[4*i+2]; l[4*i+3] = av.w - h[4*i+3];
        }
        uint4 hA = make_uint4(pkbf(h[0],h[1]), pkbf(h[2],h[3]),
                              pkbf(h[4],h[5]), pkbf(h[6],h[7]));
        uint4 hB = make_uint4(pkbf(h[8],h[9]), pkbf(h[10],h[11]),
                              pkbf(h[12],h[13]), pkbf(h[14],h[15]));
        uint4 lA = make_uint4(pkbf(l[0],l[1]), pkbf(l[2],l[3]),
                              pkbf(l[4],l[5]), pkbf(l[6],l[7]));
        uint4 lB = make_uint4(pkbf(l[8],l[9]), pkbf(l[10],l[11]),
                              pkbf(l[12],l[13]), pkbf(l[14],l[15]));
        *(uint4*)&Ab[s][0][rloc][(kq >> 1)]     = hA;
        *(uint4*)&Ab[s][0][rloc][(kq >> 1) + 4] = hB;
        *(uint4*)&Ab[s][1][rloc][(kq >> 1)]     = lA;
        *(uint4*)&Ab[s][1][rloc][(kq >> 1) + 4] = lB;
    };

    load_regs(0);
    split_store(0);
    __syncthreads();

    int KT = K >> 5;
    for (int kt = 0; kt < KT; kt++) {
        int s = kt & 1;
        if (kt + 1 < KT) load_regs((kt + 1) * 32);
        uint32_t sOff = (uint32_t)s * (2 * ABLK);

#pragma unroll
        for (int cc = 0; cc < 2; cc++) {
            int chunk = kt * 2 + cc;
            uint4 bv[8];
#pragma unroll
            for (int nt = 0; nt < 8; nt++)
                bv[nt] = Bp[(long long)((ntBase + nt) * chunksPerN + chunk) * 32 + lane];

            uint32_t kOff = (uint32_t)(cc * 8) * 4;
            uint32_t ah[2][4], al[2][4];
            ldsm4(ah[0], aBase + sOff + rowOff0 + kOff);
            ldsm4(al[0], aBase + sOff + ABLK + rowOff0 + kOff);
            ldsm4(ah[1], aBase + sOff + rowOff1 + kOff);
            ldsm4(al[1], aBase + sOff + ABLK + rowOff1 + kOff);
#pragma unroll
            for (int nt = 0; nt < 8; nt++) {
#pragma unroll
                for (int mt = 0; mt < 2; mt++) {
                    float* c = acc[mt][nt];
                    mma16816(c, ah[mt][0], ah[mt][1], ah[mt][2], ah[mt][3],
                             bv[nt].x, bv[nt].y);
                    mma16816(c, al[mt][0], al[mt][1], al[mt][2], al[mt][3],
                             bv[nt].x, bv[nt].y);
                    mma16816(c, ah[mt][0], ah[mt][1], ah[mt][2], ah[mt][3],
                             bv[nt].z, bv[nt].w);
                }
            }
        }
        if (kt + 1 < KT) split_store(s ^ 1);
        __syncthreads();
    }

    float drow[2][2] = {{0.f, 0.f}, {0.f, 0.f}};
#pragma unroll
    for (int mt = 0; mt < 2; mt++) {
        int r0 = m0 + mBase + mt * 16 + grp;
        int r1 = r0 + 8;
        float s0 = rowScal ? rowScal[r0] : 0.f;
        float s1 = rowScal ? rowScal[r1] : 0.f;
#pragma unroll
        for (int nt = 0; nt < 8; nt++) {
            int cb = n0 + wn * 64 + nt * 8 + thr * 2;
            float v00 = acc[mt][nt][0], v01 = acc[mt][nt][1];
            float v10 = acc[mt][nt][2], v11 = acc[mt][nt][3];
            if (bias) {
                float b0 = bias[cb], b1 = bias[cb + 1];
                v00 += b0; v01 += b1; v10 += b0; v11 += b1;
            }
            if (rowScal) {
                float w0 = rowVec[cb], w1 = rowVec[cb + 1];
                v00 += s0 * w0; v01 += s0 * w1;
                v10 += s1 * w0; v11 += s1 * w1;
            }
            if (doRelu) {
                v00 = fmaxf(v00, 0.f); v01 = fmaxf(v01, 0.f);
                v10 = fmaxf(v10, 0.f); v11 = fmaxf(v11, 0.f);
            }
            if (dotW) {
                float w0 = dotW[cb], w1 = dotW[cb + 1];
                drow[0][0] += 0.f;   // keep structure
                drow[mt][0] += v00 * w0 + v01 * w1;
                drow[mt][1] += v10 * w0 + v11 * w1;
            } else {
                C[(long long)r0 * ldc + cb] = v00;
                C[(long long)r0 * ldc + cb + 1] = v01;
                C[(long long)r1 * ldc + cb] = v10;
                C[(long long)r1 * ldc + cb + 1] = v11;
            }
        }
    }
    if (dotW) {
#pragma unroll
        for (int mt = 0; mt < 2; mt++)
#pragma unroll
            for (int rr = 0; rr < 2; rr++) {
                float v = drow[mt][rr];
                v += __shfl_xor_sync(0xffffffffu, v, 1);
                v += __shfl_xor_sync(0xffffffffu, v, 2);
                drow[mt][rr] = v;
            }
        if (thr == 0) {
            int slot = blockIdx.x * 2 + wn;
#pragma unroll
            for (int mt = 0; mt < 2; mt++) {
                int r0 = m0 + mBase + mt * 16 + grp;
                dotPart[(long long)r0 * 8 + slot]       = drow[mt][0];
                dotPart[(long long)(r0 + 8) * 8 + slot] = drow[mt][1];
            }
        }
    }
}

// ---------------- finalize rate: sum 8 partials + sigmoid ----------------
__global__ void k_rate(const float* __restrict__ dotPart,
                       const float* __restrict__ b2, float* __restrict__ outr) {
    int w = blockIdx.x * blockDim.x + threadIdx.x;
    if (w >= RROWS) return;
    const float* p = dotPart + (long long)w * 8;
    float s = ((p[0] + p[1]) + (p[2] + p[3])) + ((p[4] + p[5]) + (p[6] + p[7]));
    outr[w] = 1.f / (1.f + expf(-(s + b2[0])));
}

// ---------------- sigmoids: MUFU variant + poly variant (pipe balance) ----------
__device__ __forceinline__ float sigmoid_mufu(float x) {
    float t = x * -1.44269504f;
    float E; asm("ex2.approx.f32 %0, %1;" : "=f"(E) : "f"(t));
    float u = 1.f + E;
    float y; asm("rcp.approx.f32 %0, %1;" : "=f"(y) : "f"(u));
    return y;
}

__device__ __forceinline__ float sigmoid_poly(float x) {
    x = fminf(fmaxf(x, -80.f), 80.f);
    float t = x * -1.44269504f;
    float r = rintf(t);
    float f = t - r;
    float p = 1.33335581e-3f;
    p = fmaf(p, f, 9.61812910e-3f);
    p = fmaf(p, f, 5.55041086e-2f);
    p = fmaf(p, f, 2.40226507e-1f);
    p = fmaf(p, f, 6.93147181e-1f);
    p = fmaf(p, f, 1.f);
    float E = __int_as_float(((int)r + 127) << 23) * p;
    float u = 1.f + E;
    float y = __int_as_float(0x7EF311C3 - __float_as_int(u));
    y = y * fmaf(-u, y, 2.f);
    y = y * fmaf(-u, y, 2.f);
    return y;
}

// ---------------- fused GRU scan v4: 4-CTA clusters, 64 SMs ----------------
// Cluster owns 16 batches; rank r computes gate cols {g*256 + r*64 + f : f<64}
// (192 local cols via 4 MMA warps x 48 cols) and h feats [r*64,(r+1)*64).
// h (bf16) double-buffered; own 64-feat slice broadcast to 3 peers via DSMEM.
// smem: hsU[2][16][136]u32 @0 (17408) ; hfs[16][68]f @17408 (4352) ;
//       ghs[16][200]f @21760 (12800) ; gis[16][200]f @34560 (12800) = 47360
#define SCAN4_SMEM 47360
#define CLUSTER_SYNC_() do { \
    asm volatile("barrier.cluster.arrive.aligned;" ::: "memory"); \
    asm volatile("barrier.cluster.wait.aligned;"   ::: "memory"); \
} while (0)

__global__ __launch_bounds__(256) __cluster_dims__(4, 1, 1)
void k_scan4(const float* __restrict__ giAll,
             const float* __restrict__ bhh,
             const float* __restrict__ h0,
             float* __restrict__ rin)
{
    extern __shared__ char sm[];
    uint32_t* hsU = (uint32_t*)sm;                       // [2][16][136] bf16x2
    float* hfs = (float*)(sm + 17408);                   // [16][68] own feats fp32
    float* ghs = (float*)(sm + 21760);                   // [16][200]
    float* gis = (float*)(sm + 34560);                   // [16][200]

    int tid = threadIdx.x;
    int wid = tid >> 5, lane = tid & 31, grp = lane >> 2, thr = lane & 3;
    uint32_t rank; asm("mov.u32 %0, %%cluster_ctarank;" : "=r"(rank));
    int b0 = (blockIdx.x >> 2) * 16;

    // init h buffer 0 (full 256 feats bf16) + own 64-feat fp32
    for (int idx = tid; idx < 2048; idx += 256) {
        int b = idx >> 7, kp = idx & 127;
        float ha = h0[(b0 + b) * 256 + 2 * kp];
        float hb = h0[(b0 + b) * 256 + 2 * kp + 1];
        hsU[b * 136 + kp] = pkbf(ha, hb);
        if ((uint32_t)(kp >> 5) == rank) {
            int fl = 2 * (kp - (int)rank * 32);
            hfs[b * 68 + fl] = ha;
            hfs[b * 68 + fl + 1] = hb;
        }
    }

    // per-thread gate biases (2 items/thread)
    float bR[2][2], bZ[2][2], bN[2][2];
#pragma unroll
    for (int q = 0; q < 2; q++) {
        int it = q * 256 + tid;
        int f2 = it & 31;
#pragma unroll
        for (int e = 0; e < 2; e++) {
            int fe = 2 * f2 + e;
            bR[q][e] = bhh[rank * 64 + fe];
            bZ[q][e] = bhh[256 + rank * 64 + fe];
            bN[q][e] = bhh[512 + rank * 64 + fe];
        }
    }

    // prefetch gi (own 3x64 column slices) for t=0
    {
        const float* src0 = giAll + (size_t)b0 * G3 + rank * 64;
#pragma unroll
        for (int q = 0; q < 3; q++) {
            int i = q * 256 + tid;             // 0..767
            int b = i / 48, rem = i - b * 48;
            int g = rem >> 4, ch = rem & 15;
            const float* s = src0 + (size_t)b * G3 + g * 256 + ch * 4;
            asm volatile("cp.async.cg.shared.global [%0], [%1], 16;"
                         :: "r"(sm2u(&gis[b * 200 + g * 64 + ch * 4])), "l"(s));
        }
        asm volatile("cp.async.commit_group;" ::: "memory");
    }
    __syncthreads();
    CLUSTER_SYNC_();

    const uint4* wpw = g_WPK + (size_t)((rank * 4 + wid) * 48) * 32 + lane;

    for (int t = 0; t < TS; t++) {
        int s = t & 1;
        int sOff = s * 2176;
        // ---- MMA: gh_local[16 x 192] via 4 warps (wid<4), 48 cols each ----
        if (wid < 4) {
            float acc[6][4];
#pragma unroll
            for (int tt = 0; tt < 6; tt++)
#pragma unroll
                for (int q = 0; q < 4; q++) acc[tt][q] = 0.f;

#pragma unroll
            for (int c = 0; c < 16; c++) {
                uint32_t a0 = hsU[sOff + grp * 136 + c * 8 + thr];
                uint32_t a1 = hsU[sOff + (grp + 8) * 136 + c * 8 + thr];
                uint32_t a2 = hsU[sOff + grp * 136 + c * 8 + thr + 4];
                uint32_t a3 = hsU[sOff + (grp + 8) * 136 + c * 8 + thr + 4];
#pragma unroll
                for (int tp = 0; tp < 3; tp++) {
                    uint4 bv = wpw[(c * 3 + tp) * 32];
                    mma16816(acc[2 * tp],     a0, a1, a2, a3, bv.x, bv.y);
                    mma16816(acc[2 * tp + 1], a0, a1, a2, a3, bv.z, bv.w);
                }
            }
#pragma unroll
            for (int tt = 0; tt < 6; tt++) {
                int col = wid * 48 + tt * 8 + 2 * thr;
                *(float2*)&ghs[grp * 200 + col]       = make_float2(acc[tt][0], acc[tt][1]);
                *(float2*)&ghs[(grp + 8) * 200 + col] = make_float2(acc[tt][2], acc[tt][3]);
            }
        }
        asm volatile("cp.async.wait_group 0;" ::: "memory");
        __syncthreads();

        // ---- gate phase: own 64 features x 16 batches (2 items/thread) ----
        int s2Off = (s ^ 1) * 2176;
#pragma unroll
        for (int q = 0; q < 2; q++) {
            int it = q * 256 + tid;
            int b = it >> 5, f2 = it & 31;
            float h2[2];
#pragma unroll
            for (int e = 0; e < 2; e++) {
                int fe = 2 * f2 + e;
                int gb = b * 200 + fe;
                float rr = sigmoid_mufu(gis[gb] + ghs[gb] + bR[q][e]);
                float zz = sigmoid_mufu(gis[gb + 64] + ghs[gb + 64] + bZ[q][e]);
                float na = gis[gb + 128] + rr * (ghs[gb + 128] + bN[q][e]);
                float nn = fmaf(2.f, sigmoid_poly(2.f * na), -1.f);
                float hp = hfs[b * 68 + fe];
                float h = nn + zz * (hp - nn);
                hfs[b * 68 + fe] = h;
                rin[((size_t)t * BATCH + b0 + b) * 512 + rank * 64 + fe] = h;
                h2[e] = h;
            }
            uint32_t pk = pkbf(h2[0], h2[1]);
            uint32_t kp = rank * 32 + (uint32_t)f2;
            uint32_t lidx = (uint32_t)s2Off + (uint32_t)b * 136 + kp;
            hsU[lidx] = pk;                               // own copy
            uint32_t laddr = sm2u(&hsU[lidx]);
#pragma unroll
            for (int p = 1; p < 4; p++) {
                uint32_t pr = (rank + (uint32_t)p) & 3u;
                uint32_t raddr;
                asm("mapa.shared::cluster.u32 %0, %1, %2;" : "=r"(raddr)
                    : "r"(laddr), "r"(pr));
                asm volatile("st.shared::cluster.u32 [%0], %1;"
                             :: "r"(raddr), "r"(pk) : "memory");
            }
        }

        // all gis reads done -> prefetch t+1 under the cluster barrier wait
        __syncthreads();
        if (t < TS - 1) {
            const float* src0 = giAll + ((size_t)(t + 1) * BATCH + b0) * G3 + rank * 64;
#pragma unroll
            for (int q = 0; q < 3; q++) {
                int i = q * 256 + tid;
                int b = i / 48, rem = i - b * 48;
                int g = rem >> 4, ch = rem & 15;
                const float* sp = src0 + (size_t)b * G3 + g * 256 + ch * 4;
                asm volatile("cp.async.cg.shared.global [%0], [%1], 16;"
                             :: "r"(sm2u(&gis[b * 200 + g * 64 + ch * 4])), "l"(sp));
            }
            asm volatile("cp.async.commit_group;" ::: "memory");
        }
        CLUSTER_SYNC_();
    }
}

// ---------------- host launcher ----------------
extern "C" void kernel_launch(void* const* d_in, const int* in_sizes, int n_in,
                              void* d_out, int out_size) {
    const float* route_emb = (const float*)d_in[0];
    const int*   trg_id    = (const int*)  d_in[2];
    const float* trg_rate  = (const float*)d_in[3];
    const int*   mask      = (const int*)  d_in[5];
    const float* emb_id    = (const float*)d_in[6];
    const float* gat_w     = (const float*)d_in[7];
    const float* a_src     = (const float*)d_in[8];
    const float* a_dst     = (const float*)d_in[9];
    const float* gat_bias  = (const float*)d_in[10];
    const float* ln_g      = (const float*)d_in[11];
    const float* ln_b      = (const float*)d_in[12];
    const float* w_ih      = (const float*)d_in[13];
    const float* w_hh      = (const float*)d_in[14];
    const float* b_ih      = (const float*)d_in[15];
    const float* b_hh      = (const float*)d_in[16];
    const float* fc1w      = (const float*)d_in[17];
    const float* fc1b      = (const float*)d_in[18];
    const float* fc2w      = (const float*)d_in[19];
    const float* fc2b      = (const float*)d_in[20];
    float* out = (float*)d_out;

    float *XW, *ROUT, *ROUTT, *H0, *COLV, *GI, *RIN, *DOT;
    uint4 *PIH, *PF1, *PXW;
    cudaGetSymbolAddress((void**)&XW,   g_XW);
    cudaGetSymbolAddress((void**)&ROUT, g_ROUT);
    cudaGetSymbolAddress((void**)&ROUTT,g_ROUTT);
    cudaGetSymbolAddress((void**)&H0,   g_H0);
    cudaGetSymbolAddress((void**)&COLV, g_COLV);
    cudaGetSymbolAddress((void**)&GI,   g_GI);
    cudaGetSymbolAddress((void**)&RIN,  g_RIN);
    cudaGetSymbolAddress((void**)&DOT,  g_DOT);
    cudaGetSymbolAddress((void**)&PIH,  g_PIH);
    cudaGetSymbolAddress((void**)&PF1,  g_PF1);
    cudaGetSymbolAddress((void**)&PXW,  g_PXW);

    cudaFuncSetAttribute(k_scan4, cudaFuncAttributeMaxDynamicSharedMemorySize, SCAN4_SMEM);

    const long long IDSZ = (long long)TT * BATCH * SEQL;   // 8388608

    cudaStream_t s2;
    cudaStreamCreateWithFlags(&s2, cudaStreamNonBlocking);
    cudaEvent_t evFork, evS2;
    cudaEventCreateWithFlags(&evFork, cudaEventDisableTiming);
    cudaEventCreateWithFlags(&evS2, cudaEventDisableTiming);

    // ---- minimal pre-GI prep on default stream ----
    k_detect<<<1, 32>>>(trg_id);
    k_packsplitT<<<192, 256>>>(w_ih, G3, HID, 257, PIH);
    k_col<<<3, 256>>>(w_ih, COLV);

    // ---- fork: s2 runs everything else GI doesn't need ----
    cudaEventRecord(evFork, 0);
    cudaStreamWaitEvent(s2, evFork, 0);

    // default: GI = gather(emb_id) @ W_ih^T + rate*col + b_ih
    k_bgemm<<<dim3(6, 510), 256>>>(RROWS, G3, HID,
        emb_id, HID, (const void*)trg_id, PIH, GI, G3,
        trg_rate, COLV, b_ih, 0, nullptr, nullptr);

    // s2: output zeroing, packs, GAT chain
    k_memset<<<(BATCH * SEQL + 255) / 256, 256, 0, s2>>>(out, BATCH * SEQL);
    k_memset<<<1, 256, 0, s2>>>(out + IDSZ, BATCH);
    k_packsplitT<<<256, 256, 0, s2>>>(fc1w, 512, 512, 512, PF1);
    k_packsplit<<<64, 256, 0, s2>>>(gat_w, HID, HID, PXW);
    k_packbf4<<<96, 256, 0, s2>>>(w_hh);
    k_bgemm<<<dim3(2, 256), 256, 0, s2>>>(NNODE, HID, HID,
        route_emb, HID, nullptr, PXW, XW, HID,
        nullptr, nullptr, nullptr, 0, nullptr, nullptr);
    k_asd<<<NNODE * 4 / 256, 256, 0, s2>>>(a_src, a_dst);
    k_gat<<<NNODE, HID, 0, s2>>>(route_emb, gat_bias, ln_g, ln_b);
    k_hidden0<<<BATCH, HID, 0, s2>>>();
    k_routt<<<dim3(8, 4, BATCH), dim3(32, 8), 0, s2>>>();

    // ---- join: default waits for s2, then runs scan + tail ----
    cudaEventRecord(evS2, s2);
    cudaStreamWaitEvent(0, evS2, 0);

    // --- fused GRU scan: 64 blocks, 4-CTA clusters ---
    k_scan4<<<64, 256, SCAN4_SMEM>>>(GI, b_hh, H0, RIN);

    // --- scores + fused softmax (fp32) -> d_out holds final attn ---
    k_sgemm<<<dim3(1, 2, BATCH), 256>>>(TS, SEQL, HID,
        RIN, BATCH * 512, 512,
        ROUTT, SEQL, (long long)HID * SEQL,
        out + (long long)BATCH * SEQL, BATCH * SEQL, SEQL,
        mask, SEQL, 0.0625f, 1);

    // --- weighted (fp32) -> RIN right half ---
    k_sgemm<<<dim3(2, 2, BATCH), 256>>>(TS, HID, SEQL,
        out + (long long)BATCH * SEQL, BATCH * SEQL, SEQL,
        ROUT, HID, (long long)SEQL * HID,
        RIN + 256, BATCH * 512, 512,
        nullptr, 0, 1.f, 0);

    // --- rate head: fc1+fc2 fused (dot mode), then finalize sigmoid ---
    k_bgemm<<<dim3(4, 510), 256>>>(RROWS, 512, 512,
        RIN, 512, nullptr, PF1, nullptr, 0,
        nullptr, nullptr, fc1b, 1, fc2w, DOT);
    k_rate<<<(RROWS + 255) / 256, 256>>>(DOT, fc2b, out + IDSZ + BATCH);
}

// round 17
// speedup vs baseline: 1.0597x; 1.0597x over previous
#include <cuda_runtime.h>
#include <cuda_bf16.h>
#include <math.h>
#include <stdint.h>

// ---------------- problem constants ----------------
#define HID 256          // H
#define NHEAD 4
#define DHEAD 64
#define BATCH 256        // B
#define SEQL 128         // L
#define TT 256           // T
#define TS 255           // T-1 scan steps
#define RROWS (TS*BATCH) // 65280
#define NNODE (BATCH*SEQL) // 32768
#define G3 768           // 3*H

// ---------------- device scratch (static, no allocs) ----------------
__device__ int   g_is64;
__device__ int   g_flagH[256];               // scan progress: 32 arrivals per t
__device__ float g_XW[NNODE*HID];
__device__ float g_ASD[NNODE*8];
__device__ float g_ROUT[NNODE*HID];
__device__ float g_ROUTT[BATCH*HID*SEQL];
__device__ float g_H0[BATCH*HID];
__device__ float g_COLV[G3];                 // w_ih[:,256] rate column
__device__ float g_GI[RROWS*G3];
__device__ float g_RIN[RROWS*512];           // [h_t | weighted] rows
__device__ float g_DOT[RROWS*8];             // fc2 partial dots
__device__ uint4 g_WPK[24576];               // W_hh packed bf16 fragments (scan)
__device__ uint4 g_PIH[49152];               // W_ih^T packed split-bf16 fragments
__device__ uint4 g_PF1[65536];               // fc1_w^T packed split-bf16 fragments
__device__ uint4 g_PXW[16384];               // gat_w packed split-bf16 fragments

// ---------------- small utility kernels ----------------
__global__ void k_detect(const int* __restrict__ t) {
    if (threadIdx.x == 0) {
        int all0 = 1;
        for (int q = 1; q < 256; q += 2) if (t[q] != 0) { all0 = 0; break; }
        g_is64 = all0;
    }
}

__global__ void k_memset(float* p, int n) {
    int i = blockIdx.x * blockDim.x + threadIdx.x;
    if (i < n) p[i] = 0.f;
}

// spin until f[idx] >= target (1 thread; consumers follow in stream order)
__global__ void k_wait(const int* __restrict__ f, int idx, int target) {
    if (threadIdx.x == 0) {
        while (*(volatile const int*)(f + idx) < target) __nanosleep(2000);
        __threadfence();
    }
}

// extract rate column: colv[n] = w_ih[n*257 + 256]
__global__ void k_col(const float* __restrict__ wih, float* __restrict__ colv) {
    int n = blockIdx.x * blockDim.x + threadIdx.x;
    if (n < G3) colv[n] = wih[n * 257 + 256];
}

__device__ __forceinline__ uint32_t pkbf(float a, float b) {
    return (uint32_t)__bfloat16_as_ushort(__float2bfloat16(a)) |
           ((uint32_t)__bfloat16_as_ushort(__float2bfloat16(b)) << 16);
}
__device__ __forceinline__ float bfhi(float a) {
    return __bfloat162float(__float2bfloat16(a));
}

// pack W_hh (768x256 row-major) into bf16 m16n8k16 B-fragments for the 2-CTA scan.
__global__ void k_packbf2(const float* __restrict__ whh) {
    int gid = blockIdx.x * 256 + threadIdx.x;     // 0..24575
    int lane = gid & 31;
    int q = gid >> 5;                             // 0..767
    int tp3 = q % 3;
    int t2 = q / 3;
    int c = t2 & 15;
    int t3 = t2 >> 4;
    int w = t3 & 7, r = t3 >> 3;
    int grp = lane >> 2, thr = lane & 3;
    int jl0 = w * 48 + (2 * tp3) * 8 + grp;
    int jl1 = jl0 + 8;
    int j0 = (jl0 >> 7) * 256 + r * 128 + (jl0 & 127);
    int j1 = (jl1 >> 7) * 256 + r * 128 + (jl1 & 127);
    int kb = c * 16 + 2 * thr;
    const float* W0 = whh + j0 * 256;
    const float* W1 = whh + j1 * 256;
    uint4 v;
    v.x = pkbf(W0[kb],     W0[kb + 1]);
    v.y = pkbf(W0[kb + 8], W0[kb + 9]);
    v.z = pkbf(W1[kb],     W1[kb + 1]);
    v.w = pkbf(W1[kb + 8], W1[kb + 9]);
    g_WPK[gid] = v;
}

// pack K-major B[K][N] (element (k,n) at B[k*N+n]) into split-bf16 fragments.
__global__ void k_packsplit(const float* __restrict__ B, int N, int K, uint4* out) {
    int gid = blockIdx.x * 256 + threadIdx.x;
    int total = (N >> 3) * (K >> 4) * 32;
    if (gid >= total) return;
    int lane = gid & 31, q = gid >> 5;
    int chunks = K >> 4;
    int chunk = q % chunks, ntile = q / chunks;
    int grp = lane >> 2, thr = lane & 3;
    int n = ntile * 8 + grp;
    int k0 = chunk * 16 + 2 * thr;
    float x0 = B[(long long)k0 * N + n];
    float x1 = B[(long long)(k0 + 1) * N + n];
    float x2 = B[(long long)(k0 + 8) * N + n];
    float x3 = B[(long long)(k0 + 9) * N + n];
    float h0 = bfhi(x0), h1 = bfhi(x1), h2 = bfhi(x2), h3 = bfhi(x3);
    uint4 v;
    v.x = pkbf(h0, h1);
    v.y = pkbf(h2, h3);
    v.z = pkbf(x0 - h0, x1 - h1);
    v.w = pkbf(x2 - h2, x3 - h3);
    out[gid] = v;
}

// transposed source: element (k,n) at src[n*ld + k]  (row-major weights)
__global__ void k_packsplitT(const float* __restrict__ src, int N, int K, int ld,
                             uint4* out) {
    int gid = blockIdx.x * 256 + threadIdx.x;
    int total = (N >> 3) * (K >> 4) * 32;
    if (gid >= total) return;
    int lane = gid & 31, q = gid >> 5;
    int chunks = K >> 4;
    int chunk = q % chunks, ntile = q / chunks;
    int grp = lane >> 2, thr = lane & 3;
    int n = ntile * 8 + grp;
    int k0 = chunk * 16 + 2 * thr;
    const float* row = src + (long long)n * ld;
    float x0 = row[k0];
    float x1 = row[k0 + 1];
    float x2 = row[k0 + 8];
    float x3 = row[k0 + 9];
    float h0 = bfhi(x0), h1 = bfhi(x1), h2 = bfhi(x2), h3 = bfhi(x3);
    uint4 v;
    v.x = pkbf(h0, h1);
    v.y = pkbf(h2, h3);
    v.z = pkbf(x0 - h0, x1 - h1);
    v.w = pkbf(x2 - h2, x3 - h3);
    out[gid] = v;
}

// ---------------- GAT: a_src / a_dst projections ----------------
__global__ void k_asd(const float* __restrict__ asrc, const float* __restrict__ adst) {
    __shared__ float ss[HID], sd[HID];
    int t = threadIdx.x;
    ss[t] = asrc[t]; sd[t] = adst[t];
    __syncthreads();
    int gid = blockIdx.x * 256 + t;
    int n = gid >> 2, h = gid & 3;
    const float* x = &g_XW[n * HID + h * DHEAD];
    const float* cs = &ss[h * DHEAD];
    const float* cd = &sd[h * DHEAD];
    float s = 0.f, d = 0.f;
#pragma unroll 8
    for (int q = 0; q < DHEAD; q++) { float v = x[q]; s += v * cs[q]; d += v * cd[q]; }
    g_ASD[n * 8 + h] = s;
    g_ASD[n * 8 + 4 + h] = d;
}

// ---------------- GAT aggregate + residual + LayerNorm ----------------
__global__ void k_gat(const float* __restrict__ emb, const float* __restrict__ bias,
                      const float* __restrict__ gamma, const float* __restrict__ beta) {
    int i = blockIdx.x;
    int j = threadIdx.x;
    int h = j >> 6;
    int l = i & (SEQL - 1);
    float ad = g_ASD[i * 8 + 4 + h];
    bool v0 = (l > 0), v1 = (l < SEQL - 1);
    float e0 = -1e30f, e1 = -1e30f;
    if (v0) { float e = g_ASD[(i - 1) * 8 + h] + ad; e0 = e > 0.f ? e : 0.2f * e; }
    if (v1) { float e = g_ASD[(i + 1) * 8 + h] + ad; e1 = e > 0.f ? e : 0.2f * e; }
    float emax = fmaxf(e0, e1);
    float x0 = v0 ? expf(e0 - emax) : 0.f;
    float x1 = v1 ? expf(e1 - emax) : 0.f;
    float inv = 1.f / (x0 + x1 + 1e-16f);
    float a0 = x0 * inv, a1 = x1 * inv;
    float val = bias[j] + emb[(long long)i * HID + j];
    if (v0) val += a0 * g_XW[(i - 1) * HID + j];
    if (v1) val += a1 * g_XW[(i + 1) * HID + j];
    __shared__ float red[HID];
    red[j] = val; __syncthreads();
    for (int s = 128; s > 0; s >>= 1) { if (j < s) red[j] += red[j + s]; __syncthreads(); }
    float mean = red[0] * (1.f / HID); __syncthreads();
    float dv = val - mean;
    red[j] = dv * dv; __syncthreads();
    for (int s = 128; s > 0; s >>= 1) { if (j < s) red[j] += red[j + s]; __syncthreads(); }
    float var = red[0] * (1.f / HID);
    g_ROUT[(long long)i * HID + j] = dv * rsqrtf(var + 1e-5f) * gamma[j] + beta[j];
}

__global__ void k_hidden0() {
    int b = blockIdx.x, j = threadIdx.x;
    const float* p = &g_ROUT[(long long)b * SEQL * HID + j];
    float s = 0.f;
    for (int l = 0; l < SEQL; l++) s += p[l * HID];
    g_H0[b * HID + j] = s * (1.f / SEQL);
}

// (b,l,h) -> (b,h,l)
__global__ void k_routt() {
    __shared__ float tile[32][33];
    int b = blockIdx.z;
    int h0 = blockIdx.x * 32, l0 = blockIdx.y * 32;
    int x = threadIdx.x, y = threadIdx.y;
    const float* in = &g_ROUT[(long long)b * SEQL * HID];
    float* out = &g_ROUTT[(long long)b * HID * SEQL];
    for (int yy = y; yy < 32; yy += 8) tile[yy][x] = in[(l0 + yy) * HID + h0 + x];
    __syncthreads();
    for (int yy = y; yy < 32; yy += 8) out[(h0 + yy) * SEQL + l0 + x] = tile[x][yy];
}

// ---------------- generic tiled fp32 SGEMM (scores / weighted) ----------------
// doSoftmax: requires gridDim.x==1 (full N row per block); writes softmaxed,
// mask-zeroed attn directly.
__global__ __launch_bounds__(256, 2) void k_sgemm(
    int M, int N, int K,
    const float* __restrict__ A, int lda, long long sA,
    const float* __restrict__ B, int ldb, long long sB,
    float* __restrict__ C, int ldc, long long sC,
    const int* __restrict__ maskPtr, int maskStride,
    float alpha, int doSoftmax)
{
    __shared__ float As[8][128];
    __shared__ float Bs[8][128];
    const float* Ab = A + (long long)blockIdx.z * sA;
    const float* Bb = B + (long long)blockIdx.z * sB;
    float* Cb = C + (long long)blockIdx.z * sC;
    int m0 = blockIdx.y * 128, n0 = blockIdx.x * 128;
    int tid = threadIdx.x, tx = tid & 15, ty = tid >> 4;
    float acc[8][8];
#pragma unroll
    for (int i = 0; i < 8; i++)
#pragma unroll
        for (int j = 0; j < 8; j++) acc[i][j] = 0.f;

    int rowL = tid >> 1, kq = (tid & 1) * 4;
    int grow = m0 + rowL; if (grow > M - 1) grow = M - 1;
    const float* Arow = Ab + (long long)grow * lda;
    int kB = tid >> 5, nq = (tid & 31) * 4;

    for (int k0 = 0; k0 < K; k0 += 8) {
        float4 av = *(const float4*)(Arow + k0 + kq);
        As[kq + 0][rowL] = av.x; As[kq + 1][rowL] = av.y;
        As[kq + 2][rowL] = av.z; As[kq + 3][rowL] = av.w;
        *(float4*)&Bs[kB][nq] = *(const float4*)(Bb + (long long)(k0 + kB) * ldb + n0 + nq);
        __syncthreads();
#pragma unroll
        for (int kk = 0; kk < 8; kk++) {
            float a[8], b[8];
            *(float4*)&a[0] = *(const float4*)&As[kk][ty * 4];
            *(float4*)&a[4] = *(const float4*)&As[kk][64 + ty * 4];
            *(float4*)&b[0] = *(const float4*)&Bs[kk][tx * 4];
            *(float4*)&b[4] = *(const float4*)&Bs[kk][64 + tx * 4];
#pragma unroll
            for (int i = 0; i < 8; i++)
#pragma unroll
                for (int j = 0; j < 8; j++) acc[i][j] += a[i] * b[j];
        }
        __syncthreads();
    }

    if (doSoftmax) {
        const int* mkz = maskPtr + (long long)blockIdx.z * maskStride;
#pragma unroll
        for (int i = 0; i < 8; i++) {
            int mloc = (i < 4) ? ty * 4 + i : 64 + ty * 4 + (i - 4);
            int m = m0 + mloc;
            float v[8]; int nl[8]; int vld[8];
#pragma unroll
            for (int j = 0; j < 8; j++) {
                nl[j] = (j < 4) ? tx * 4 + j : 64 + tx * 4 + (j - 4);
                vld[j] = mkz[n0 + nl[j]];
                float x = acc[i][j] * alpha;
                v[j] = vld[j] ? x : -1e30f;
            }
            float mx = v[0];
#pragma unroll
            for (int j = 1; j < 8; j++) mx = fmaxf(mx, v[j]);
            for (int o = 1; o < 16; o <<= 1)
                mx = fmaxf(mx, __shfl_xor_sync(0xffffffffu, mx, o));
            float s = 0.f;
#pragma unroll
            for (int j = 0; j < 8; j++) { v[j] = expf(v[j] - mx); s += v[j]; }
            for (int o = 1; o < 16; o <<= 1)
                s += __shfl_xor_sync(0xffffffffu, s, o);
            float inv = 1.f / s;
            if (m < M) {
#pragma unroll
                for (int j = 0; j < 8; j++)
                    Cb[(long long)m * ldc + n0 + nl[j]] = vld[j] ? v[j] * inv : 0.f;
            }
        }
        return;
    }

#pragma unroll
    for (int i = 0; i < 8; i++) {
        int mloc = (i < 4) ? ty * 4 + i : 64 + ty * 4 + (i - 4);
        int m = m0 + mloc;
        if (m >= M) continue;
#pragma unroll
        for (int j = 0; j < 8; j++) {
            int nloc = (j < 4) ? tx * 4 + j : 64 + tx * 4 + (j - 4);
            int n = n0 + nloc;
            Cb[(long long)m * ldc + n] = acc[i][j] * alpha;
        }
    }
}

// ---------------- bf16 mma + helpers ----------------
__device__ __forceinline__ void mma16816(float* c, uint32_t a0, uint32_t a1,
                                         uint32_t a2, uint32_t a3,
                                         uint32_t b0, uint32_t b1) {
    asm volatile(
        "mma.sync.aligned.m16n8k16.row.col.f32.bf16.bf16.f32 "
        "{%0,%1,%2,%3},{%4,%5,%6,%7},{%8,%9},{%0,%1,%2,%3};"
        : "+f"(c[0]), "+f"(c[1]), "+f"(c[2]), "+f"(c[3])
        : "r"(a0), "r"(a1), "r"(a2), "r"(a3), "r"(b0), "r"(b1));
}

__device__ __forceinline__ uint32_t sm2u(const void* p) {
    return (uint32_t)__cvta_generic_to_shared(p);
}

__device__ __forceinline__ void ldsm4(uint32_t* d, uint32_t saddr) {
    asm volatile("ldmatrix.sync.aligned.m8n8.x4.shared.b16 {%0,%1,%2,%3}, [%4];"
        : "=r"(d[0]), "=r"(d[1]), "=r"(d[2]), "=r"(d[3]) : "r"(saddr));
}

// ---------------- split-bf16 GEMM (double-buffered A, ldmatrix fragments) --------
#define ABLK (128*20*4)          // bytes of one [128][20] u32 block
__global__ __launch_bounds__(256, 2) void k_bgemm(
    int M, int N, int K,
    const float* __restrict__ A, int lda,
    const void* __restrict__ gth,
    const uint4* __restrict__ Bp,
    float* __restrict__ C, int ldc,
    const float* __restrict__ rowScal, const float* __restrict__ rowVec,
    const float* __restrict__ bias, int doRelu,
    const float* __restrict__ dotW, float* __restrict__ dotPart)
{
    __shared__ uint32_t Ab[2][2][128][20];

    int m0 = blockIdx.y * 128, n0 = blockIdx.x * 128;
    int tid = threadIdx.x;

    int rloc = tid >> 1, kq = (tid & 1) * 16;
    const float* Arow;
    {
        int grow = m0 + rloc;
        if (gth) {
            long long gr = g_is64 ? ((const long long*)gth)[grow]
                                  : (long long)((const int*)gth)[grow];
            Arow = A + gr * (long long)lda;
        } else {
            Arow = A + (long long)grow * lda;
        }
    }

    int wid = tid >> 5, lane = tid & 31;
    int wm = wid & 3, wn = wid >> 2;
    int mBase = wm * 32;
    int grp = lane >> 2, thr = lane & 3;
    int chunksPerN = K >> 4;
    int ntBase = (n0 >> 3) + wn * 8;

    uint32_t aBase = sm2u(&Ab[0][0][lane & 15][(lane >> 4) << 2]);
    uint32_t rowOff0 = (uint32_t)(mBase) * 80;
    uint32_t rowOff1 = (uint32_t)(mBase + 16) * 80;

    float acc[2][8][4];
#pragma unroll
    for (int mt = 0; mt < 2; mt++)
#pragma unroll
        for (int nt = 0; nt < 8; nt++)
#pragma unroll
            for (int q = 0; q < 4; q++) acc[mt][nt][q] = 0.f;

    float4 avr[4];
    auto load_regs = [&](int k0) {
#pragma unroll
        for (int i = 0; i < 4; i++)
            avr[i] = *(const float4*)(Arow + k0 + kq + 4 * i);
    };
    auto split_store = [&](int s) {
        float h[16], l[16];
#pragma unroll
        for (int i = 0; i < 4; i++) {
            float4 av = avr[i];
            h[4*i+0] = bfhi(av.x); h[4*i+1] = bfhi(av.y);
            h[4*i+2] = bfhi(av.z); h[4*i+3] = bfhi(av.w);
            l[4*i+0] = av.x - h[4*i+0]; l[4*i+1] = av.y - h[4*i+1];
            l[4*i+2] = av.z - h[4*i+2]; l[4*i+3] = av.w - h[4*i+3];
        }
        uint4 hA = make_uint4(pkbf(h[0],h[1]), pkbf(h[2],h[3]),
                              pkbf(h[4],h[5]), pkbf(h[6],h[7]));
        uint4 hB = make_uint4(pkbf(h[8],h[9]), pkbf(h[10],h[11]),
                              pkbf(h[12],h[13]), pkbf(h[14],h[15]));
        uint4 lA = make_uint4(pkbf(l[0],l[1]), pkbf(l[2],l[3]),
                              pkbf(l[4],l[5]), pkbf(l[6],l[7]));
        uint4 lB = make_uint4(pkbf(l[8],l[9]), pkbf(l[10],l[11]),
                              pkbf(l[12],l[13]), pkbf(l[14],l[15]));
        *(uint4*)&Ab[s][0][rloc][(kq >> 1)]     = hA;
        *(uint4*)&Ab[s][0][rloc][(kq >> 1) + 4] = hB;
        *(uint4*)&Ab[s][1][rloc][(kq >> 1)]     = lA;
        *(uint4*)&Ab[s][1][rloc][(kq >> 1) + 4] = lB;
    };

    load_regs(0);
    split_store(0);
    __syncthreads();

    int KT = K >> 5;
    for (int kt = 0; kt < KT; kt++) {
        int s = kt & 1;
        if (kt + 1 < KT) load_regs((kt + 1) * 32);
        uint32_t sOff = (uint32_t)s * (2 * ABLK);

#pragma unroll
        for (int cc = 0; cc < 2; cc++) {
            int chunk = kt * 2 + cc;
            uint4 bv[8];
#pragma unroll
            for (int nt = 0; nt < 8; nt++)
                bv[nt] = Bp[(long long)((ntBase + nt) * chunksPerN + chunk) * 32 + lane];

            uint32_t kOff = (uint32_t)(cc * 8) * 4;
            uint32_t ah[2][4], al[2][4];
            ldsm4(ah[0], aBase + sOff + rowOff0 + kOff);
            ldsm4(al[0], aBase + sOff + ABLK + rowOff0 + kOff);
            ldsm4(ah[1], aBase + sOff + rowOff1 + kOff);
            ldsm4(al[1], aBase + sOff + ABLK + rowOff1 + kOff);
#pragma unroll
            for (int nt = 0; nt < 8; nt++) {
#pragma unroll
                for (int mt = 0; mt < 2; mt++) {
                    float* c = acc[mt][nt];
                    mma16816(c, ah[mt][0], ah[mt][1], ah[mt][2], ah[mt][3],
                             bv[nt].x, bv[nt].y);
                    mma16816(c, al[mt][0], al[mt][1], al[mt][2], al[mt][3],
                             bv[nt].x, bv[nt].y);
                    mma16816(c, ah[mt][0], ah[mt][1], ah[mt][2], ah[mt][3],
                             bv[nt].z, bv[nt].w);
                }
            }
        }
        if (kt + 1 < KT) split_store(s ^ 1);
        __syncthreads();
    }

    float drow[2][2] = {{0.f, 0.f}, {0.f, 0.f}};
#pragma unroll
    for (int mt = 0; mt < 2; mt++) {
        int r0 = m0 + mBase + mt * 16 + grp;
        int r1 = r0 + 8;
        float s0 = rowScal ? rowScal[r0] : 0.f;
        float s1 = rowScal ? rowScal[r1] : 0.f;
#pragma unroll
        for (int nt = 0; nt < 8; nt++) {
            int cb = n0 + wn * 64 + nt * 8 + thr * 2;
            float v00 = acc[mt][nt][0], v01 = acc[mt][nt][1];
            float v10 = acc[mt][nt][2], v11 = acc[mt][nt][3];
            if (bias) {
                float b0 = bias[cb], b1 = bias[cb + 1];
                v00 += b0; v01 += b1; v10 += b0; v11 += b1;
            }
            if (rowScal) {
                float w0 = rowVec[cb], w1 = rowVec[cb + 1];
                v00 += s0 * w0; v01 += s0 * w1;
                v10 += s1 * w0; v11 += s1 * w1;
            }
            if (doRelu) {
                v00 = fmaxf(v00, 0.f); v01 = fmaxf(v01, 0.f);
                v10 = fmaxf(v10, 0.f); v11 = fmaxf(v11, 0.f);
            }
            if (dotW) {
                float w0 = dotW[cb], w1 = dotW[cb + 1];
                drow[mt][0] += v00 * w0 + v01 * w1;
                drow[mt][1] += v10 * w0 + v11 * w1;
            } else {
                C[(long long)r0 * ldc + cb] = v00;
                C[(long long)r0 * ldc + cb + 1] = v01;
                C[(long long)r1 * ldc + cb] = v10;
                C[(long long)r1 * ldc + cb + 1] = v11;
            }
        }
    }
    if (dotW) {
#pragma unroll
        for (int mt = 0; mt < 2; mt++)
#pragma unroll
            for (int rr = 0; rr < 2; rr++) {
                float v = drow[mt][rr];
                v += __shfl_xor_sync(0xffffffffu, v, 1);
                v += __shfl_xor_sync(0xffffffffu, v, 2);
                drow[mt][rr] = v;
            }
        if (thr == 0) {
            int slot = blockIdx.x * 2 + wn;
#pragma unroll
            for (int mt = 0; mt < 2; mt++) {
                int r0 = m0 + mBase + mt * 16 + grp;
                dotPart[(long long)r0 * 8 + slot]       = drow[mt][0];
                dotPart[(long long)(r0 + 8) * 8 + slot] = drow[mt][1];
            }
        }
    }
}

// ---------------- finalize rate: sum 8 partials + sigmoid ----------------
__global__ void k_rate(const float* __restrict__ dotPart,
                       const float* __restrict__ b2, float* __restrict__ outr) {
    int w = blockIdx.x * blockDim.x + threadIdx.x;
    if (w >= RROWS) return;
    const float* p = dotPart + (long long)w * 8;
    float s = ((p[0] + p[1]) + (p[2] + p[3])) + ((p[4] + p[5]) + (p[6] + p[7]));
    outr[w] = 1.f / (1.f + expf(-(s + b2[0])));
}

// ---------------- sigmoids: MUFU variant + poly variant (pipe balance) ----------
__device__ __forceinline__ float sigmoid_mufu(float x) {
    float t = x * -1.44269504f;
    float E; asm("ex2.approx.f32 %0, %1;" : "=f"(E) : "f"(t));
    float u = 1.f + E;
    float y; asm("rcp.approx.f32 %0, %1;" : "=f"(y) : "f"(u));
    return y;
}

__device__ __forceinline__ float sigmoid_poly(float x) {
    x = fminf(fmaxf(x, -80.f), 80.f);
    float t = x * -1.44269504f;
    float r = rintf(t);
    float f = t - r;
    float p = 1.33335581e-3f;
    p = fmaf(p, f, 9.61812910e-3f);
    p = fmaf(p, f, 5.55041086e-2f);
    p = fmaf(p, f, 2.40226507e-1f);
    p = fmaf(p, f, 6.93147181e-1f);
    p = fmaf(p, f, 1.f);
    float E = __int_as_float(((int)r + 127) << 23) * p;
    float u = 1.f + E;
    float y = __int_as_float(0x7EF311C3 - __float_as_int(u));
    y = y * fmaf(-u, y, 2.f);
    y = y * fmaf(-u, y, 2.f);
    return y;
}

// ---------------- fused GRU scan: 2-CTA clusters, 32 SMs, progress flags -------
#define SCAN2_SMEM 76032
#define CLUSTER_SYNC_() do { \
    asm volatile("barrier.cluster.arrive.aligned;" ::: "memory"); \
    asm volatile("barrier.cluster.wait.aligned;"   ::: "memory"); \
} while (0)

__global__ __launch_bounds__(256) __cluster_dims__(2, 1, 1)
void k_scan2(const float* __restrict__ giAll,
             const float* __restrict__ bhh,
             const float* __restrict__ h0,
             float* __restrict__ rin,
             int* flagH)
{
    extern __shared__ char sm[];
    uint32_t* hsU = (uint32_t*)sm;                       // [2][16][136] bf16x2
    float* hfs = (float*)(sm + 17408);                   // [16][132] own-half fp32
    float* ghs = (float*)(sm + 25856);                   // [16][392]
    float* gis = (float*)(sm + 50944);                   // [16][392]

    int tid = threadIdx.x;
    int wid = tid >> 5, lane = tid & 31, grp = lane >> 2, thr = lane & 3;
    uint32_t rank; asm("mov.u32 %0, %%cluster_ctarank;" : "=r"(rank));
    uint32_t peer = 1u - rank;
    int b0 = (blockIdx.x >> 1) * 16;

    for (int idx = tid; idx < 2048; idx += 256) {
        int b = idx >> 7, kp = idx & 127;
        float ha = h0[(b0 + b) * 256 + 2 * kp];
        float hb = h0[(b0 + b) * 256 + 2 * kp + 1];
        hsU[b * 136 + kp] = pkbf(ha, hb);
        if ((uint32_t)(kp >> 6) == rank) {
            int fl = 2 * (kp - (int)rank * 64);
            hfs[b * 132 + fl] = ha;
            hfs[b * 132 + fl + 1] = hb;
        }
    }

    float bR[4][2], bZ[4][2], bN[4][2];
#pragma unroll
    for (int q = 0; q < 4; q++) {
        int it = q * 256 + tid;
        int f2 = it & 63;
#pragma unroll
        for (int e = 0; e < 2; e++) {
            int fe = 2 * f2 + e;
            bR[q][e] = bhh[rank * 128 + fe];
            bZ[q][e] = bhh[256 + rank * 128 + fe];
            bN[q][e] = bhh[512 + rank * 128 + fe];
        }
    }

    {
        const float* src0 = giAll + (size_t)b0 * G3 + rank * 128;
#pragma unroll
        for (int q = 0; q < 6; q++) {
            int i = q * 256 + tid;
            int b = i / 96, rem = i - b * 96;
            int g = rem >> 5, ch = rem & 31;
            const float* s = src0 + (size_t)b * G3 + g * 256 + ch * 4;
            asm volatile("cp.async.cg.shared.global [%0], [%1], 16;"
                         :: "r"(sm2u(&gis[b * 392 + g * 128 + ch * 4])), "l"(s));
        }
        asm volatile("cp.async.commit_group;" ::: "memory");
    }
    __syncthreads();
    CLUSTER_SYNC_();

    const uint4* wpw = g_WPK + (size_t)((rank * 8 + wid) * 48) * 32 + lane;

    for (int t = 0; t < TS; t++) {
        int s = t & 1;
        int sOff = s * 2176;
        float acc[6][4];
#pragma unroll
        for (int tt = 0; tt < 6; tt++)
#pragma unroll
            for (int q = 0; q < 4; q++) acc[tt][q] = 0.f;

#pragma unroll
        for (int c = 0; c < 16; c++) {
            uint32_t a0 = hsU[sOff + grp * 136 + c * 8 + thr];
            uint32_t a1 = hsU[sOff + (grp + 8) * 136 + c * 8 + thr];
            uint32_t a2 = hsU[sOff + grp * 136 + c * 8 + thr + 4];
            uint32_t a3 = hsU[sOff + (grp + 8) * 136 + c * 8 + thr + 4];
#pragma unroll
            for (int tp = 0; tp < 3; tp++) {
                uint4 bv = wpw[(c * 3 + tp) * 32];
                mma16816(acc[2 * tp],     a0, a1, a2, a3, bv.x, bv.y);
                mma16816(acc[2 * tp + 1], a0, a1, a2, a3, bv.z, bv.w);
            }
        }
#pragma unroll
        for (int tt = 0; tt < 6; tt++) {
            int col = wid * 48 + tt * 8 + 2 * thr;
            *(float2*)&ghs[grp * 392 + col]       = make_float2(acc[tt][0], acc[tt][1]);
            *(float2*)&ghs[(grp + 8) * 392 + col] = make_float2(acc[tt][2], acc[tt][3]);
        }
        asm volatile("cp.async.wait_group 0;" ::: "memory");
        __syncthreads();

        int s2Off = (s ^ 1) * 2176;
#pragma unroll
        for (int q = 0; q < 4; q++) {
            int it = q * 256 + tid;
            int b = it >> 6, f2 = it & 63;
            float h2[2];
#pragma unroll
            for (int e = 0; e < 2; e++) {
                int fe = 2 * f2 + e;
                int gb = b * 392 + fe;
                float rr = sigmoid_mufu(gis[gb] + ghs[gb] + bR[q][e]);
                float zz = sigmoid_mufu(gis[gb + 128] + ghs[gb + 128] + bZ[q][e]);
                float na = gis[gb + 256] + rr * (ghs[gb + 256] + bN[q][e]);
                float nn = fmaf(2.f, sigmoid_poly(2.f * na), -1.f);
                float hp = hfs[b * 132 + fe];
                float h = nn + zz * (hp - nn);
                hfs[b * 132 + fe] = h;
                rin[((size_t)t * BATCH + b0 + b) * 512 + rank * 128 + fe] = h;
                h2[e] = h;
            }
            uint32_t pk = pkbf(h2[0], h2[1]);
            uint32_t kp = rank * 64 + (uint32_t)f2;
            uint32_t lidx = (uint32_t)s2Off + (uint32_t)b * 136 + kp;
            hsU[lidx] = pk;
            uint32_t laddr = sm2u(&hsU[lidx]);
            uint32_t raddr;
            asm("mapa.shared::cluster.u32 %0, %1, %2;" : "=r"(raddr)
                : "r"(laddr), "r"(peer));
            asm volatile("st.shared::cluster.u32 [%0], %1;"
                         :: "r"(raddr), "r"(pk) : "memory");
        }

        // all gis reads done -> prefetch t+1 under the cluster barrier wait
        __syncthreads();
        if (t < TS - 1) {
            const float* src0 = giAll + ((size_t)(t + 1) * BATCH + b0) * G3 + rank * 128;
#pragma unroll
            for (int q = 0; q < 6; q++) {
                int i = q * 256 + tid;
                int b = i / 96, rem = i - b * 96;
                int g = rem >> 5, ch = rem & 31;
                const float* sp = src0 + (size_t)b * G3 + g * 256 + ch * 4;
                asm volatile("cp.async.cg.shared.global [%0], [%1], 16;"
                             :: "r"(sm2u(&gis[b * 392 + g * 128 + ch * 4])), "l"(sp));
            }
            asm volatile("cp.async.commit_group;" ::: "memory");
        }
        // publish progress: h for step t is globally visible
        if (tid == 0) {
            __threadfence();
            atomicAdd(&flagH[t], 1);
        }
        CLUSTER_SYNC_();
    }
}

// ---------------- host launcher ----------------
extern "C" void kernel_launch(void* const* d_in, const int* in_sizes, int n_in,
                              void* d_out, int out_size) {
    const float* route_emb = (const float*)d_in[0];
    const int*   trg_id    = (const int*)  d_in[2];
    const float* trg_rate  = (const float*)d_in[3];
    const int*   mask      = (const int*)  d_in[5];
    const float* emb_id    = (const float*)d_in[6];
    const float* gat_w     = (const float*)d_in[7];
    const float* a_src     = (const float*)d_in[8];
    const float* a_dst     = (const float*)d_in[9];
    const float* gat_bias  = (const float*)d_in[10];
    const float* ln_g      = (const float*)d_in[11];
    const float* ln_b      = (const float*)d_in[12];
    const float* w_ih      = (const float*)d_in[13];
    const float* w_hh      = (const float*)d_in[14];
    const float* b_ih      = (const float*)d_in[15];
    const float* b_hh      = (const float*)d_in[16];
    const float* fc1w      = (const float*)d_in[17];
    const float* fc1b      = (const float*)d_in[18];
    const float* fc2w      = (const float*)d_in[19];
    const float* fc2b      = (const float*)d_in[20];
    float* out = (float*)d_out;

    float *XW, *ROUT, *ROUTT, *H0, *COLV, *GI, *RIN, *DOT;
    uint4 *PIH, *PF1, *PXW;
    int *FLAGH;
    cudaGetSymbolAddress((void**)&XW,   g_XW);
    cudaGetSymbolAddress((void**)&ROUT, g_ROUT);
    cudaGetSymbolAddress((void**)&ROUTT,g_ROUTT);
    cudaGetSymbolAddress((void**)&H0,   g_H0);
    cudaGetSymbolAddress((void**)&COLV, g_COLV);
    cudaGetSymbolAddress((void**)&GI,   g_GI);
    cudaGetSymbolAddress((void**)&RIN,  g_RIN);
    cudaGetSymbolAddress((void**)&DOT,  g_DOT);
    cudaGetSymbolAddress((void**)&PIH,  g_PIH);
    cudaGetSymbolAddress((void**)&PF1,  g_PF1);
    cudaGetSymbolAddress((void**)&PXW,  g_PXW);
    cudaGetSymbolAddress((void**)&FLAGH, g_flagH);

    cudaFuncSetAttribute(k_scan2, cudaFuncAttributeMaxDynamicSharedMemorySize, SCAN2_SMEM);

    const long long IDSZ = (long long)TT * BATCH * SEQL;   // 8388608

    cudaStream_t s2;
    cudaStreamCreateWithFlags(&s2, cudaStreamNonBlocking);
    cudaEvent_t evFork, evS2, evDone;
    cudaEventCreateWithFlags(&evFork, cudaEventDisableTiming);
    cudaEventCreateWithFlags(&evS2, cudaEventDisableTiming);
    cudaEventCreateWithFlags(&evDone, cudaEventDisableTiming);

    // ---- minimal pre-GI prep on default stream (also zero the flags) ----
    k_detect<<<1, 32>>>(trg_id);
    k_memset<<<1, 256>>>((float*)FLAGH, 256);
    k_packsplitT<<<192, 256>>>(w_ih, G3, HID, 257, PIH);
    k_col<<<3, 256>>>(w_ih, COLV);

    // ---- fork ----
    cudaEventRecord(evFork, 0);
    cudaStreamWaitEvent(s2, evFork, 0);

    // default: GI = gather(emb_id) @ W_ih^T + rate*col + b_ih
    k_bgemm<<<dim3(6, 510), 256>>>(RROWS, G3, HID,
        emb_id, HID, (const void*)trg_id, PIH, GI, G3,
        trg_rate, COLV, b_ih, 0, nullptr, nullptr);

    // s2: output zeroing, packs, GAT chain (hidden under GI)
    k_memset<<<(BATCH * SEQL + 255) / 256, 256, 0, s2>>>(out, BATCH * SEQL);
    k_memset<<<1, 256, 0, s2>>>(out + IDSZ, BATCH);
    k_packsplitT<<<256, 256, 0, s2>>>(fc1w, 512, 512, 512, PF1);
    k_packsplit<<<64, 256, 0, s2>>>(gat_w, HID, HID, PXW);
    k_packbf2<<<96, 256, 0, s2>>>(w_hh);
    k_bgemm<<<dim3(2, 256), 256, 0, s2>>>(NNODE, HID, HID,
        route_emb, HID, nullptr, PXW, XW, HID,
        nullptr, nullptr, nullptr, 0, nullptr, nullptr);
    k_asd<<<NNODE * 4 / 256, 256, 0, s2>>>(a_src, a_dst);
    k_gat<<<NNODE, HID, 0, s2>>>(route_emb, gat_bias, ln_g, ln_b);
    k_hidden0<<<BATCH, HID, 0, s2>>>();
    k_routt<<<dim3(8, 4, BATCH), dim3(32, 8), 0, s2>>>();
    cudaEventRecord(evS2, s2);

    // default: scan waits for GI (program order) + GAT deps, grabs its SMs first
    cudaStreamWaitEvent(0, evS2, 0);
    k_scan2<<<32, 256, SCAN2_SMEM>>>(GI, b_hh, H0, RIN, FLAGH);

    // s2: tail, pipelined in two t-halves (does NOT wait for full scan)
    const long long ATTN = (long long)BATCH * SEQL;   // attn base offset in out

    // --- A half: t in [0,128) ---
    k_wait<<<1, 32, 0, s2>>>(FLAGH, 127, 32);
    k_sgemm<<<dim3(1, 1, BATCH), 256, 0, s2>>>(128, SEQL, HID,
        RIN, BATCH * 512, 512,
        ROUTT, SEQL, (long long)HID * SEQL,
        out + ATTN, BATCH * SEQL, SEQL,
        mask, SEQL, 0.0625f, 1);
    k_sgemm<<<dim3(2, 1, BATCH), 256, 0, s2>>>(128, HID, SEQL,
        out + ATTN, BATCH * SEQL, SEQL,
        ROUT, HID, (long long)SEQL * HID,
        RIN + 256, BATCH * 512, 512,
        nullptr, 0, 1.f, 0);
    k_bgemm<<<dim3(4, 256), 256, 0, s2>>>(128 * BATCH, 512, 512,
        RIN, 512, nullptr, PF1, nullptr, 0,
        nullptr, nullptr, fc1b, 1, fc2w, DOT);

    // --- B half: t in [128,255) ---
    k_wait<<<1, 32, 0, s2>>>(FLAGH, 254, 32);
    k_sgemm<<<dim3(1, 1, BATCH), 256, 0, s2>>>(127, SEQL, HID,
        RIN + 128LL * BATCH * 512, BATCH * 512, 512,
        ROUTT, SEQL, (long long)HID * SEQL,
        out + ATTN + 128LL * BATCH * SEQL, BATCH * SEQL, SEQL,
        mask, SEQL, 0.0625f, 1);
    k_sgemm<<<dim3(2, 1, BATCH), 256, 0, s2>>>(127, HID, SEQL,
        out + ATTN + 128LL * BATCH * SEQL, BATCH * SEQL, SEQL,
        ROUT, HID, (long long)SEQL * HID,
        RIN + 256 + 128LL * BATCH * 512, BATCH * 512, 512,
        nullptr, 0, 1.f, 0);
    k_bgemm<<<dim3(4, 254), 256, 0, s2>>>(127 * BATCH, 512, 512,
        RIN + 128LL * BATCH * 512, 512, nullptr, PF1, nullptr, 0,
        nullptr, nullptr, fc1b, 1, fc2w, DOT + 128LL * BATCH * 8);

    // --- finalize rate ---
    k_rate<<<(RROWS + 255) / 256, 256, 0, s2>>>(DOT, fc2b, out + IDSZ + BATCH);

    // ---- join s2 back into the default stream ----
    cudaEventRecord(evDone, s2);
    cudaStreamWaitEvent(0, evDone, 0);
}